// round 14
// baseline (speedup 1.0000x reference)
#include <cuda_runtime.h>
#include <cstdint>

#define BATCH 8
#define CCH   256
#define WID   4096
#define GROUPS 3

// fp32 scratch: qkv[g*256+o][b][j]
__device__ float g_qkv[(size_t)GROUPS * CCH * BATCH * WID];
// tf32-rounded operands (stored as fp32)
__device__ float g_xt[(size_t)BATCH * CCH * WID];
__device__ float g_wt[(size_t)GROUPS * CCH * CCH];

// ---------------------------------------------------------------------------
__device__ __forceinline__ uint32_t sptr(const void* p) {
    return (uint32_t)__cvta_generic_to_shared(p);
}
__device__ __forceinline__ float tf32r(float f) {
    uint32_t r;
    asm("cvt.rna.tf32.f32 %0, %1;" : "=r"(r) : "f"(f));
    return __uint_as_float(r);
}
__device__ __forceinline__ void mma_tf32(float* c, const uint32_t* a,
                                         uint32_t b0, uint32_t b1) {
    asm volatile(
        "mma.sync.aligned.m16n8k8.row.col.f32.tf32.tf32.f32 "
        "{%0,%1,%2,%3}, {%4,%5,%6,%7}, {%8,%9}, {%0,%1,%2,%3};"
        : "+f"(c[0]), "+f"(c[1]), "+f"(c[2]), "+f"(c[3])
        : "r"(a[0]), "r"(a[1]), "r"(a[2]), "r"(a[3]), "r"(b0), "r"(b1));
}
#define CP16(dst, src) \
    asm volatile("cp.async.cg.shared.global [%0], [%1], 16;" :: "r"(dst), "l"(src))
#define CP_COMMIT() asm volatile("cp.async.commit_group;")
#define CP_WAIT(n)  asm volatile("cp.async.wait_group %0;" :: "n"(n))

// ---------------------------------------------------------------------------
// Kernel 0: tf32-round fp32 operands; parameterized x-range, optional W part.
// ---------------------------------------------------------------------------
#define NX4 (BATCH * CCH * WID / 4)   // 2097152 float4 in x
#define NW4 (CCH * CCH / 4)           // 16384 float4 per weight
#define NXB (NX4 / 8)                 // 262144 float4 per batch

__global__ __launch_bounds__(256)
void convert_tf32(const float* __restrict__ x, const float* __restrict__ wq,
                  const float* __restrict__ wk, const float* __restrict__ wv,
                  int nx4, int xbase, int withW)
{
    int idx = blockIdx.x * 256 + threadIdx.x;
    if (idx < nx4) {
        int e = xbase + idx;
        float4 v = ((const float4*)x)[e];
        v.x = tf32r(v.x); v.y = tf32r(v.y); v.z = tf32r(v.z); v.w = tf32r(v.w);
        ((float4*)g_xt)[e] = v;
    } else if (withW) {
        int r = idx - nx4;
        if (r < 3 * NW4) {
            int g = r / NW4, e = r % NW4;
            const float* W = (g == 0) ? wq : (g == 1) ? wk : wv;
            float4 v = ((const float4*)W)[e];
            v.x = tf32r(v.x); v.y = tf32r(v.y); v.z = tf32r(v.z); v.w = tf32r(v.w);
            ((float4*)g_wt)[g * NW4 + e] = v;
        }
    }
}

// ---------------------------------------------------------------------------
// Kernel 1: tf32 GEMM, single pass. CTA 128m x 128n, k-chunk 32, 3-stage
// cp.async. Stage (35328 B): A[128][36]f32 @0 (18432 B), B[32][132]f32 @18432.
// Strides 36/132 floats => bank = 4*row + col pattern, conflict-free.
// ---------------------------------------------------------------------------
#define STAGE_BYTES 35328
#define SMEM_GEMM   (3 * STAGE_BYTES)   // 105984

__device__ __forceinline__ void prefetch_chunk(
    char* s, int stage, int tid,
    const float* __restrict__ wtg, const float* __restrict__ xtb,
    int kc, int j0)
{
    uint32_t base = sptr(s + stage * STAGE_BYTES);
    #pragma unroll
    for (int i = 0; i < 4; ++i) {               // A: 128 rows x 8 segs
        int e = tid + i * 256;
        int row = e >> 3, seg = e & 7;
        CP16(base + (uint32_t)(row * 36 + seg * 4) * 4,
             wtg + (size_t)row * CCH + kc + seg * 4);
    }
    #pragma unroll
    for (int i = 0; i < 4; ++i) {               // B: 32 rows x 32 segs
        int e = tid + i * 256;
        int row = e >> 5, seg = e & 31;
        CP16(base + 18432 + (uint32_t)(row * 132 + seg * 4) * 4,
             xtb + (size_t)(kc + row) * WID + j0 + seg * 4);
    }
}

__global__ __launch_bounds__(256, 2)
void qkv_gemm_tf32(int bb)
{
    extern __shared__ char smem[];

    const int nt = blockIdx.x;
    const int my = blockIdx.y;
    const int b  = blockIdx.z + bb;
    const int g  = my >> 1;
    const int m0g = (my & 1) * 128;
    const int j0 = nt * 128;

    const float* wtg = g_wt + (size_t)g * CCH * CCH + (size_t)m0g * CCH;
    const float* xtb = g_xt + (size_t)b * CCH * WID;

    const int tid  = threadIdx.x;
    const int lane = tid & 31;
    const int wid  = tid >> 5;
    const int wm   = wid >> 2;        // 0..1 (64-row slabs)
    const int wn   = wid & 3;         // 0..3 (32-col slabs)
    const int lr   = lane >> 2;       // 0..7
    const int lc   = lane & 3;        // 0..3

    float acc[4][4][4];
    #pragma unroll
    for (int i = 0; i < 4; ++i)
        #pragma unroll
        for (int j = 0; j < 4; ++j)
            #pragma unroll
            for (int r = 0; r < 4; ++r) acc[i][j][r] = 0.f;

    prefetch_chunk(smem, 0, tid, wtg, xtb, 0, j0);
    CP_COMMIT();
    prefetch_chunk(smem, 1, tid, wtg, xtb, 32, j0);
    CP_COMMIT();

    #pragma unroll 1
    for (int kc8 = 0; kc8 < 8; ++kc8) {
        const int stage = kc8 % 3;
        if (kc8 < 7) { CP_WAIT(1); } else { CP_WAIT(0); }
        __syncthreads();

        const float* As = (const float*)(smem + stage * STAGE_BYTES);
        const float* Bs = (const float*)(smem + stage * STAGE_BYTES + 18432);

        #pragma unroll
        for (int ks = 0; ks < 4; ++ks) {        // 4 k8-steps per 32-chunk
            const int c0 = ks * 8 + lc;
            // B fragments: 4 n-atoms
            uint32_t bf[4][2];
            #pragma unroll
            for (int na = 0; na < 4; ++na) {
                int n0 = wn * 32 + na * 8 + lr;
                bf[na][0] = __float_as_uint(Bs[c0 * 132 + n0]);
                bf[na][1] = __float_as_uint(Bs[(c0 + 4) * 132 + n0]);
            }
            // A fragments: 4 m-atoms
            uint32_t af[4][4];
            #pragma unroll
            for (int ma = 0; ma < 4; ++ma) {
                int r0 = wm * 64 + ma * 16 + lr;
                af[ma][0] = __float_as_uint(As[r0 * 36 + c0]);
                af[ma][1] = __float_as_uint(As[(r0 + 8) * 36 + c0]);
                af[ma][2] = __float_as_uint(As[r0 * 36 + c0 + 4]);
                af[ma][3] = __float_as_uint(As[(r0 + 8) * 36 + c0 + 4]);
            }
            #pragma unroll
            for (int ma = 0; ma < 4; ++ma)
                #pragma unroll
                for (int na = 0; na < 4; ++na)
                    mma_tf32(acc[ma][na], af[ma], bf[na][0], bf[na][1]);
        }
        __syncthreads();

        if (kc8 < 6) {
            prefetch_chunk(smem, (kc8 + 2) % 3, tid, wtg, xtb, (kc8 + 2) * 32, j0);
            CP_COMMIT();
        }
    }

    // epilogue (C fragment layout identical to 16816)
    #pragma unroll
    for (int ma = 0; ma < 4; ++ma) {
        int r0 = m0g + wm * 64 + ma * 16 + lr;
        #pragma unroll
        for (int na = 0; na < 4; ++na) {
            int jj = j0 + wn * 32 + na * 8 + lc * 2;
            float* d0 = g_qkv + ((size_t)(g * 256 + r0) * BATCH + b) * WID + jj;
            float* d1 = d0 + (size_t)8 * BATCH * WID;
            *(float2*)d0 = make_float2(acc[ma][na][0], acc[ma][na][1]);
            *(float2*)d1 = make_float2(acc[ma][na][2], acc[ma][na][3]);
        }
    }
}

// ---------------------------------------------------------------------------
// Kernel 2: windowed softmax, 8 outputs/thread, no max-sub, fast divide.
// ---------------------------------------------------------------------------
__global__ __launch_bounds__(256)
void attn_window8(float* __restrict__ out, int bb)
{
    int t8 = blockIdx.x * 256 + threadIdx.x;
    int w  = (t8 & 511) * 8;
    int t  = (t8 >> 9) + bb * 256;   // b*256 + o
    int o  = t & 255;
    int b  = t >> 8;

    const float* Q = g_qkv + ((size_t)o * BATCH + b) * WID;
    const float* K = Q + (size_t)256 * BATCH * WID;
    const float* V = Q + (size_t)512 * BATCH * WID;

    const float4 z4 = make_float4(0.f, 0.f, 0.f, 0.f);
    float4 q0 = *(const float4*)(Q + w);
    float4 q1 = *(const float4*)(Q + w + 4);
    float4 km = (w >= 4)      ? *(const float4*)(K + w - 4) : z4;
    float4 k0 = *(const float4*)(K + w);
    float4 k1 = *(const float4*)(K + w + 4);
    float4 kp = (w + 8 < WID) ? *(const float4*)(K + w + 8) : z4;
    float4 vm = (w >= 4)      ? *(const float4*)(V + w - 4) : z4;
    float4 v0 = *(const float4*)(V + w);
    float4 v1 = *(const float4*)(V + w + 4);
    float4 vp = (w + 8 < WID) ? *(const float4*)(V + w + 8) : z4;

    float kk[14] = {km.y, km.z, km.w, k0.x, k0.y, k0.z, k0.w,
                    k1.x, k1.y, k1.z, k1.w, kp.x, kp.y, kp.z};
    float vv[14] = {vm.y, vm.z, vm.w, v0.x, v0.y, v0.z, v0.w,
                    v1.x, v1.y, v1.z, v1.w, vp.x, vp.y, vp.z};
    float qv[8]  = {q0.x, q0.y, q0.z, q0.w, q1.x, q1.y, q1.z, q1.w};

    float res[8];
    #pragma unroll
    for (int tt = 0; tt < 8; ++tt) {
        float sum = 0.f, accn = 0.f;
        #pragma unroll
        for (int i = 0; i < 7; ++i) {
            float e = __expf(qv[tt] * kk[tt + i]);
            sum += e;
            accn = fmaf(e, vv[tt + i], accn);
        }
        res[tt] = __fdividef(accn, sum);
    }
    float* dst = out + (size_t)t * WID + w;
    *(float4*)dst       = make_float4(res[0], res[1], res[2], res[3]);
    *(float4*)(dst + 4) = make_float4(res[4], res[5], res[6], res[7]);
}

// ---------------------------------------------------------------------------
// Stream context (created at load time; no device memory). Chunks 1..3 run on
// priority-ordered side streams (chunk 0 on the capturing main stream).
// ---------------------------------------------------------------------------
namespace {
struct StreamCtx {
    cudaStream_t s[3];
    cudaEvent_t evFork, evConvW, evJoin[3];
    StreamCtx() {
        int lo = 0, hi = 0;
        cudaDeviceGetStreamPriorityRange(&lo, &hi);
        for (int i = 0; i < 3; ++i) {
            int pr = hi + 1 + i;
            if (pr > lo) pr = lo;
            cudaStreamCreateWithPriority(&s[i], cudaStreamNonBlocking, pr);
        }
        cudaEventCreateWithFlags(&evFork,  cudaEventDisableTiming);
        cudaEventCreateWithFlags(&evConvW, cudaEventDisableTiming);
        for (int i = 0; i < 3; ++i)
            cudaEventCreateWithFlags(&evJoin[i], cudaEventDisableTiming);
    }
};
StreamCtx g_sc;

cudaStream_t pick_main_stream() {
    cudaStreamCaptureStatus st = cudaStreamCaptureStatusNone;
    if (cudaStreamGetCaptureInfo(cudaStreamPerThread, &st) == cudaSuccess &&
        st == cudaStreamCaptureStatusActive)
        return cudaStreamPerThread;
    return cudaStreamLegacy;
}
} // namespace

// ---------------------------------------------------------------------------
extern "C" void kernel_launch(void* const* d_in, const int* in_sizes, int n_in,
                              void* d_out, int out_size)
{
    (void)in_sizes; (void)n_in; (void)out_size;
    const float* x  = (const float*)d_in[0];
    const float* wq = (const float*)d_in[1];
    const float* wk = (const float*)d_in[2];
    const float* wv = (const float*)d_in[3];
    float* out = (float*)d_out;

    cudaFuncSetAttribute(qkv_gemm_tf32, cudaFuncAttributeMaxDynamicSharedMemorySize, SMEM_GEMM);

    cudaStream_t ms = pick_main_stream();

    // asymmetric chunks: head and tail small
    static const int bstart[4] = {0, 1, 4, 7};
    static const int bcount[4] = {1, 3, 3, 1};

    // fork
    cudaEventRecord(g_sc.evFork, ms);
    for (int i = 0; i < 3; ++i)
        cudaStreamWaitEvent(g_sc.s[i], g_sc.evFork, 0);

    // chunk 0 conversion (W + batch 0) on ms
    convert_tf32<<<(bcount[0] * NXB + 3 * NW4 + 255) / 256, 256, 0, ms>>>(
        x, wq, wk, wv, bcount[0] * NXB, 0, 1);
    cudaEventRecord(g_sc.evConvW, ms);

    // chunks 1..3 conversion on their streams (x only)
    for (int c = 1; c < 4; ++c)
        convert_tf32<<<(bcount[c] * NXB) / 256, 256, 0, g_sc.s[c - 1]>>>(
            x, wq, wk, wv, bcount[c] * NXB, bstart[c] * NXB, 0);

    // chunk 0 GEMM + attn on ms
    {
        dim3 grid(32, 6, bcount[0]);
        qkv_gemm_tf32<<<grid, 256, SMEM_GEMM, ms>>>(bstart[0]);
        attn_window8<<<bcount[0] * 512, 256, 0, ms>>>(out, bstart[0]);
    }

    // chunks 1..3: wait W event, then GEMM + attn
    for (int c = 1; c < 4; ++c) {
        cudaStream_t st = g_sc.s[c - 1];
        cudaStreamWaitEvent(st, g_sc.evConvW, 0);
        dim3 grid(32, 6, bcount[c]);
        qkv_gemm_tf32<<<grid, 256, SMEM_GEMM, st>>>(bstart[c]);
        attn_window8<<<bcount[c] * 512, 256, 0, st>>>(out, bstart[c]);
    }

    // join
    for (int c = 1; c < 4; ++c) {
        cudaEventRecord(g_sc.evJoin[c - 1], g_sc.s[c - 1]);
        cudaStreamWaitEvent(ms, g_sc.evJoin[c - 1], 0);
    }
}

// round 15
// speedup vs baseline: 1.7690x; 1.7690x over previous
#include <cuda_runtime.h>
#include <cuda_fp16.h>
#include <cstdint>

#define BATCH 8
#define CCH   256
#define WID   4096
#define GROUPS 3

// fp32 scratch: qkv[g*256+o][b][j]
__device__ float g_qkv[(size_t)GROUPS * CCH * BATCH * WID];
// operands: x split hi/lo (fp16), W rounded to fp16 (hi only)
__device__ __half g_xh[(size_t)BATCH * CCH * WID];
__device__ __half g_xl[(size_t)BATCH * CCH * WID];
__device__ __half g_wh[(size_t)GROUPS * CCH * CCH];

// ---------------------------------------------------------------------------
__device__ __forceinline__ uint32_t sptr(const void* p) {
    return (uint32_t)__cvta_generic_to_shared(p);
}
__device__ __forceinline__ void split2h(float f0, float f1, uint32_t& h, uint32_t& l) {
    __half h0 = __float2half_rn(f0);
    __half h1 = __float2half_rn(f1);
    __half l0 = __float2half_rn(f0 - __half2float(h0));
    __half l1 = __float2half_rn(f1 - __half2float(h1));
    h = (uint32_t)__half_as_ushort(h0) | ((uint32_t)__half_as_ushort(h1) << 16);
    l = (uint32_t)__half_as_ushort(l0) | ((uint32_t)__half_as_ushort(l1) << 16);
}
__device__ __forceinline__ void ldsm_x4(uint32_t addr, uint32_t* r) {
    asm volatile("ldmatrix.sync.aligned.m8n8.x4.shared.b16 {%0,%1,%2,%3}, [%4];"
                 : "=r"(r[0]), "=r"(r[1]), "=r"(r[2]), "=r"(r[3]) : "r"(addr));
}
__device__ __forceinline__ void ldsm_x4_t(uint32_t addr, uint32_t& r0, uint32_t& r1,
                                          uint32_t& r2, uint32_t& r3) {
    asm volatile("ldmatrix.sync.aligned.m8n8.x4.trans.shared.b16 {%0,%1,%2,%3}, [%4];"
                 : "=r"(r0), "=r"(r1), "=r"(r2), "=r"(r3) : "r"(addr));
}
__device__ __forceinline__ void mma_f16(float* c, const uint32_t* a,
                                        uint32_t b0, uint32_t b1) {
    asm volatile(
        "mma.sync.aligned.m16n8k16.row.col.f32.f16.f16.f32 "
        "{%0,%1,%2,%3}, {%4,%5,%6,%7}, {%8,%9}, {%0,%1,%2,%3};"
        : "+f"(c[0]), "+f"(c[1]), "+f"(c[2]), "+f"(c[3])
        : "r"(a[0]), "r"(a[1]), "r"(a[2]), "r"(a[3]), "r"(b0), "r"(b1));
}
#define CP16(dst, src) \
    asm volatile("cp.async.cg.shared.global [%0], [%1], 16;" :: "r"(dst), "l"(src))
#define CP_COMMIT() asm volatile("cp.async.commit_group;")
#define CP_WAIT(n)  asm volatile("cp.async.wait_group %0;" :: "n"(n))

// ---------------------------------------------------------------------------
// Kernel 0: x -> fp16 hi/lo split; W -> fp16 (round only).
// ---------------------------------------------------------------------------
#define NX4 (BATCH * CCH * WID / 4)   // 2097152 float4 in x
#define NW4 (CCH * CCH / 4)           // 16384 float4 per weight
#define NXB (NX4 / 8)                 // 262144 float4 per batch

__global__ __launch_bounds__(256)
void convert_split(const float* __restrict__ x, const float* __restrict__ wq,
                   const float* __restrict__ wk, const float* __restrict__ wv,
                   int nx4, int xbase, int withW)
{
    int idx = blockIdx.x * 256 + threadIdx.x;
    if (idx < nx4) {
        int e = xbase + idx;
        float4 v = ((const float4*)x)[e];
        uint32_t h01, l01, h23, l23;
        split2h(v.x, v.y, h01, l01);
        split2h(v.z, v.w, h23, l23);
        ((uint2*)g_xh)[e] = make_uint2(h01, h23);
        ((uint2*)g_xl)[e] = make_uint2(l01, l23);
    } else if (withW) {
        int r = idx - nx4;
        if (r < 3 * NW4) {
            int g = r / NW4, e = r % NW4;
            const float* W = (g == 0) ? wq : (g == 1) ? wk : wv;
            float4 v = ((const float4*)W)[e];
            __half2 p01 = make_half2(__float2half_rn(v.x), __float2half_rn(v.y));
            __half2 p23 = make_half2(__float2half_rn(v.z), __float2half_rn(v.w));
            ((uint2*)g_wh)[g * NW4 + e] =
                make_uint2(*(uint32_t*)&p01, *(uint32_t*)&p23);
        }
    }
}

// ---------------------------------------------------------------------------
// Kernel 1: fp16 GEMM, 2 passes (Wh*xh + Wh*xl). CTA 128m x 128n, k-chunk 32,
// 3-stage cp.async. Stage (27648 B): Ah[128][40]@0, Bh[32][136]@10240,
// Bl[32][136]@18944.
// ---------------------------------------------------------------------------
#define STAGE_BYTES 27648
#define SMEM_GEMM   (3 * STAGE_BYTES)   // 82944

__device__ __forceinline__ void prefetch_chunk(
    char* s, int stage, int tid,
    const __half* __restrict__ whg,
    const __half* __restrict__ xhb, const __half* __restrict__ xlb,
    int kc, int j0)
{
    uint32_t base = sptr(s + stage * STAGE_BYTES);
    // A (W hi): 128 rows x 4 segs of 8 halves
    #pragma unroll
    for (int i = 0; i < 2; ++i) {
        int e = tid + i * 256;
        int row = e >> 2, seg = e & 3;
        uint32_t off = (uint32_t)(row * 40 + seg * 8) * 2;
        CP16(base + off, whg + (size_t)row * CCH + kc + seg * 8);
    }
    // B (x hi + lo): 32 rows x 16 segs of 8 halves
    #pragma unroll
    for (int i = 0; i < 2; ++i) {
        int e = tid + i * 256;
        int row = e >> 4, seg = e & 15;
        uint32_t off = (uint32_t)(row * 136 + seg * 8) * 2;
        CP16(base + 10240 + off, xhb + (size_t)(kc + row) * WID + j0 + seg * 8);
        CP16(base + 18944 + off, xlb + (size_t)(kc + row) * WID + j0 + seg * 8);
    }
}

__global__ __launch_bounds__(256, 2)
void qkv_gemm_mma(int bb)
{
    extern __shared__ char smem[];

    const int nt = blockIdx.x;
    const int my = blockIdx.y;
    const int b  = blockIdx.z + bb;
    const int g  = my >> 1;
    const int m0g = (my & 1) * 128;
    const int j0 = nt * 128;

    const __half* whg = g_wh + (size_t)g * CCH * CCH + (size_t)m0g * CCH;
    const __half* xhb = g_xh + (size_t)b * CCH * WID;
    const __half* xlb = g_xl + (size_t)b * CCH * WID;

    const int tid  = threadIdx.x;
    const int lane = tid & 31;
    const int wid  = tid >> 5;
    const int wm   = wid >> 2;
    const int wn   = wid & 3;
    const int ltt  = lane >> 3;
    const int ltr  = lane & 7;

    float acc[4][4][4];
    #pragma unroll
    for (int i = 0; i < 4; ++i)
        #pragma unroll
        for (int j = 0; j < 4; ++j)
            #pragma unroll
            for (int r = 0; r < 4; ++r) acc[i][j][r] = 0.f;

    prefetch_chunk(smem, 0, tid, whg, xhb, xlb, 0, j0);
    CP_COMMIT();
    prefetch_chunk(smem, 1, tid, whg, xhb, xlb, 32, j0);
    CP_COMMIT();

    #pragma unroll 1
    for (int kc8 = 0; kc8 < 8; ++kc8) {
        const int stage = kc8 % 3;
        if (kc8 < 7) { CP_WAIT(1); } else { CP_WAIT(0); }
        __syncthreads();

        const char* sbuf = smem + stage * STAGE_BYTES;
        const __half* Ahp = (const __half*)(sbuf);
        const __half* Bhp = (const __half*)(sbuf + 10240);
        const __half* Blp = (const __half*)(sbuf + 18944);

        #pragma unroll
        for (int ks = 0; ks < 2; ++ks) {
            const int kb = ks * 16;
            uint32_t bh[4][2], bl[4][2];
            #pragma unroll
            for (int np = 0; np < 2; ++np) {
                int krow = kb + (ltt & 1) * 8 + ltr;
                int ncol = wn * 32 + np * 16 + (ltt >> 1) * 8;
                ldsm_x4_t(sptr(Bhp + krow * 136 + ncol),
                          bh[np * 2][0], bh[np * 2][1],
                          bh[np * 2 + 1][0], bh[np * 2 + 1][1]);
                ldsm_x4_t(sptr(Blp + krow * 136 + ncol),
                          bl[np * 2][0], bl[np * 2][1],
                          bl[np * 2 + 1][0], bl[np * 2 + 1][1]);
            }
            uint32_t ah[4][4];
            #pragma unroll
            for (int ma = 0; ma < 4; ++ma) {
                int row = wm * 64 + ma * 16 + (ltt & 1) * 8 + ltr;
                int col = kb + (ltt >> 1) * 8;
                ldsm_x4(sptr(Ahp + row * 40 + col), ah[ma]);
            }
            // pass 1: Wh * xh
            #pragma unroll
            for (int ma = 0; ma < 4; ++ma)
                #pragma unroll
                for (int na = 0; na < 4; ++na)
                    mma_f16(acc[ma][na], ah[ma], bh[na][0], bh[na][1]);
            // pass 2: Wh * xl
            #pragma unroll
            for (int ma = 0; ma < 4; ++ma)
                #pragma unroll
                for (int na = 0; na < 4; ++na)
                    mma_f16(acc[ma][na], ah[ma], bl[na][0], bl[na][1]);
        }
        __syncthreads();

        if (kc8 < 6) {
            prefetch_chunk(smem, (kc8 + 2) % 3, tid, whg, xhb, xlb, (kc8 + 2) * 32, j0);
            CP_COMMIT();
        }
    }

    #pragma unroll
    for (int ma = 0; ma < 4; ++ma) {
        int r0 = m0g + wm * 64 + ma * 16 + (lane >> 2);
        #pragma unroll
        for (int na = 0; na < 4; ++na) {
            int jj = j0 + wn * 32 + na * 8 + (lane & 3) * 2;
            float* d0 = g_qkv + ((size_t)(g * 256 + r0) * BATCH + b) * WID + jj;
            float* d1 = d0 + (size_t)8 * BATCH * WID;
            *(float2*)d0 = make_float2(acc[ma][na][0], acc[ma][na][1]);
            *(float2*)d1 = make_float2(acc[ma][na][2], acc[ma][na][3]);
        }
    }
}

// ---------------------------------------------------------------------------
// Kernel 2: windowed softmax, 8 outputs/thread, no max-sub, fast divide.
// ---------------------------------------------------------------------------
__global__ __launch_bounds__(256)
void attn_window8(float* __restrict__ out, int bb)
{
    int t8 = blockIdx.x * 256 + threadIdx.x;
    int w  = (t8 & 511) * 8;
    int t  = (t8 >> 9) + bb * 256;   // b*256 + o
    int o  = t & 255;
    int b  = t >> 8;

    const float* Q = g_qkv + ((size_t)o * BATCH + b) * WID;
    const float* K = Q + (size_t)256 * BATCH * WID;
    const float* V = Q + (size_t)512 * BATCH * WID;

    const float4 z4 = make_float4(0.f, 0.f, 0.f, 0.f);
    float4 q0 = *(const float4*)(Q + w);
    float4 q1 = *(const float4*)(Q + w + 4);
    float4 km = (w >= 4)      ? *(const float4*)(K + w - 4) : z4;
    float4 k0 = *(const float4*)(K + w);
    float4 k1 = *(const float4*)(K + w + 4);
    float4 kp = (w + 8 < WID) ? *(const float4*)(K + w + 8) : z4;
    float4 vm = (w >= 4)      ? *(const float4*)(V + w - 4) : z4;
    float4 v0 = *(const float4*)(V + w);
    float4 v1 = *(const float4*)(V + w + 4);
    float4 vp = (w + 8 < WID) ? *(const float4*)(V + w + 8) : z4;

    float kk[14] = {km.y, km.z, km.w, k0.x, k0.y, k0.z, k0.w,
                    k1.x, k1.y, k1.z, k1.w, kp.x, kp.y, kp.z};
    float vv[14] = {vm.y, vm.z, vm.w, v0.x, v0.y, v0.z, v0.w,
                    v1.x, v1.y, v1.z, v1.w, vp.x, vp.y, vp.z};
    float qv[8]  = {q0.x, q0.y, q0.z, q0.w, q1.x, q1.y, q1.z, q1.w};

    float res[8];
    #pragma unroll
    for (int tt = 0; tt < 8; ++tt) {
        float sum = 0.f, accn = 0.f;
        #pragma unroll
        for (int i = 0; i < 7; ++i) {
            float e = __expf(qv[tt] * kk[tt + i]);
            sum += e;
            accn = fmaf(e, vv[tt + i], accn);
        }
        res[tt] = __fdividef(accn, sum);
    }
    float* dst = out + (size_t)t * WID + w;
    *(float4*)dst       = make_float4(res[0], res[1], res[2], res[3]);
    *(float4*)(dst + 4) = make_float4(res[4], res[5], res[6], res[7]);
}

// ---------------------------------------------------------------------------
// Stream context (created at load time; no device memory). Chunks 1..3 run on
// priority-ordered side streams (chunk 0 on the capturing main stream).
// ---------------------------------------------------------------------------
namespace {
struct StreamCtx {
    cudaStream_t s[3];
    cudaEvent_t evFork, evConvW, evJoin[3];
    StreamCtx() {
        int lo = 0, hi = 0;
        cudaDeviceGetStreamPriorityRange(&lo, &hi);
        for (int i = 0; i < 3; ++i) {
            int pr = hi + 1 + i;
            if (pr > lo) pr = lo;
            cudaStreamCreateWithPriority(&s[i], cudaStreamNonBlocking, pr);
        }
        cudaEventCreateWithFlags(&evFork,  cudaEventDisableTiming);
        cudaEventCreateWithFlags(&evConvW, cudaEventDisableTiming);
        for (int i = 0; i < 3; ++i)
            cudaEventCreateWithFlags(&evJoin[i], cudaEventDisableTiming);
    }
};
StreamCtx g_sc;

cudaStream_t pick_main_stream() {
    cudaStreamCaptureStatus st = cudaStreamCaptureStatusNone;
    if (cudaStreamGetCaptureInfo(cudaStreamPerThread, &st) == cudaSuccess &&
        st == cudaStreamCaptureStatusActive)
        return cudaStreamPerThread;
    return cudaStreamLegacy;
}
} // namespace

// ---------------------------------------------------------------------------
extern "C" void kernel_launch(void* const* d_in, const int* in_sizes, int n_in,
                              void* d_out, int out_size)
{
    (void)in_sizes; (void)n_in; (void)out_size;
    const float* x  = (const float*)d_in[0];
    const float* wq = (const float*)d_in[1];
    const float* wk = (const float*)d_in[2];
    const float* wv = (const float*)d_in[3];
    float* out = (float*)d_out;

    cudaFuncSetAttribute(qkv_gemm_mma, cudaFuncAttributeMaxDynamicSharedMemorySize, SMEM_GEMM);

    cudaStream_t ms = pick_main_stream();

    // asymmetric chunks: head and tail small
    static const int bstart[4] = {0, 1, 4, 7};
    static const int bcount[4] = {1, 3, 3, 1};

    // fork
    cudaEventRecord(g_sc.evFork, ms);
    for (int i = 0; i < 3; ++i)
        cudaStreamWaitEvent(g_sc.s[i], g_sc.evFork, 0);

    // chunk 0 conversion (W + batch 0) on ms
    convert_split<<<(bcount[0] * NXB + 3 * NW4 + 255) / 256, 256, 0, ms>>>(
        x, wq, wk, wv, bcount[0] * NXB, 0, 1);
    cudaEventRecord(g_sc.evConvW, ms);

    // chunks 1..3 conversion on their streams (x only)
    for (int c = 1; c < 4; ++c)
        convert_split<<<(bcount[c] * NXB) / 256, 256, 0, g_sc.s[c - 1]>>>(
            x, wq, wk, wv, bcount[c] * NXB, bstart[c] * NXB, 0);

    // chunk 0 GEMM + attn on ms
    {
        dim3 grid(32, 6, bcount[0]);
        qkv_gemm_mma<<<grid, 256, SMEM_GEMM, ms>>>(bstart[0]);
        attn_window8<<<bcount[0] * 512, 256, 0, ms>>>(out, bstart[0]);
    }

    // chunks 1..3: wait W event, then GEMM + attn
    for (int c = 1; c < 4; ++c) {
        cudaStream_t st = g_sc.s[c - 1];
        cudaStreamWaitEvent(st, g_sc.evConvW, 0);
        dim3 grid(32, 6, bcount[c]);
        qkv_gemm_mma<<<grid, 256, SMEM_GEMM, st>>>(bstart[c]);
        attn_window8<<<bcount[c] * 512, 256, 0, st>>>(out, bstart[c]);
    }

    // join
    for (int c = 1; c < 4; ++c) {
        cudaEventRecord(g_sc.evJoin[c - 1], g_sc.s[c - 1]);
        cudaStreamWaitEvent(ms, g_sc.evJoin[c - 1], 0);
    }
}

// round 16
// speedup vs baseline: 2.2549x; 1.2747x over previous
#include <cuda_runtime.h>
#include <cuda_fp16.h>
#include <cstdint>

#define BATCH 8
#define CCH   256
#define WID   4096
#define GROUPS 3

// fp32 scratch: qkv[g*256+o][b][j]
__device__ float g_qkv[(size_t)GROUPS * CCH * BATCH * WID];
// fp16-rounded operands (single digit)
__device__ __half g_xh[(size_t)BATCH * CCH * WID];
__device__ __half g_wh[(size_t)GROUPS * CCH * CCH];

// ---------------------------------------------------------------------------
__device__ __forceinline__ uint32_t sptr(const void* p) {
    return (uint32_t)__cvta_generic_to_shared(p);
}
__device__ __forceinline__ void ldsm_x4(uint32_t addr, uint32_t* r) {
    asm volatile("ldmatrix.sync.aligned.m8n8.x4.shared.b16 {%0,%1,%2,%3}, [%4];"
                 : "=r"(r[0]), "=r"(r[1]), "=r"(r[2]), "=r"(r[3]) : "r"(addr));
}
__device__ __forceinline__ void ldsm_x4_t(uint32_t addr, uint32_t& r0, uint32_t& r1,
                                          uint32_t& r2, uint32_t& r3) {
    asm volatile("ldmatrix.sync.aligned.m8n8.x4.trans.shared.b16 {%0,%1,%2,%3}, [%4];"
                 : "=r"(r0), "=r"(r1), "=r"(r2), "=r"(r3) : "r"(addr));
}
__device__ __forceinline__ void mma_f16(float* c, const uint32_t* a,
                                        uint32_t b0, uint32_t b1) {
    asm volatile(
        "mma.sync.aligned.m16n8k16.row.col.f32.f16.f16.f32 "
        "{%0,%1,%2,%3}, {%4,%5,%6,%7}, {%8,%9}, {%0,%1,%2,%3};"
        : "+f"(c[0]), "+f"(c[1]), "+f"(c[2]), "+f"(c[3])
        : "r"(a[0]), "r"(a[1]), "r"(a[2]), "r"(a[3]), "r"(b0), "r"(b1));
}
#define CP16(dst, src) \
    asm volatile("cp.async.cg.shared.global [%0], [%1], 16;" :: "r"(dst), "l"(src))
#define CP_COMMIT() asm volatile("cp.async.commit_group;")
#define CP_WAIT(n)  asm volatile("cp.async.wait_group %0;" :: "n"(n))

// ---------------------------------------------------------------------------
// Kernel 0: round x and W to fp16.
// ---------------------------------------------------------------------------
#define NX4 (BATCH * CCH * WID / 4)   // 2097152 float4 in x
#define NW4 (CCH * CCH / 4)           // 16384 float4 per weight
#define NXB (NX4 / 8)                 // 262144 float4 per batch

__global__ __launch_bounds__(256)
void convert_h(const float* __restrict__ x, const float* __restrict__ wq,
               const float* __restrict__ wk, const float* __restrict__ wv,
               int nx4, int xbase, int withW)
{
    int idx = blockIdx.x * 256 + threadIdx.x;
    if (idx < nx4) {
        int e = xbase + idx;
        float4 v = ((const float4*)x)[e];
        __half2 p01 = make_half2(__float2half_rn(v.x), __float2half_rn(v.y));
        __half2 p23 = make_half2(__float2half_rn(v.z), __float2half_rn(v.w));
        ((uint2*)g_xh)[e] = make_uint2(*(uint32_t*)&p01, *(uint32_t*)&p23);
    } else if (withW) {
        int r = idx - nx4;
        if (r < 3 * NW4) {
            int g = r / NW4, e = r % NW4;
            const float* W = (g == 0) ? wq : (g == 1) ? wk : wv;
            float4 v = ((const float4*)W)[e];
            __half2 p01 = make_half2(__float2half_rn(v.x), __float2half_rn(v.y));
            __half2 p23 = make_half2(__float2half_rn(v.z), __float2half_rn(v.w));
            ((uint2*)g_wh)[g * NW4 + e] =
                make_uint2(*(uint32_t*)&p01, *(uint32_t*)&p23);
        }
    }
}

// ---------------------------------------------------------------------------
// Kernel 1: fp16 GEMM, single pass. CTA 128m x 128n, k-chunk 32, 3-stage
// cp.async. Stage (18944 B): Ah[128][40]@0, Bh[32][136]@10240.
// ---------------------------------------------------------------------------
#define STAGE_BYTES 18944
#define SMEM_GEMM   (3 * STAGE_BYTES)   // 56832

__device__ __forceinline__ void prefetch_chunk(
    char* s, int stage, int tid,
    const __half* __restrict__ whg, const __half* __restrict__ xhb,
    int kc, int j0)
{
    uint32_t base = sptr(s + stage * STAGE_BYTES);
    // A (W): 128 rows x 4 segs of 8 halves = 512 CP16
    #pragma unroll
    for (int i = 0; i < 2; ++i) {
        int e = tid + i * 256;
        int row = e >> 2, seg = e & 3;
        uint32_t off = (uint32_t)(row * 40 + seg * 8) * 2;
        CP16(base + off, whg + (size_t)row * CCH + kc + seg * 8);
    }
    // B (x): 32 rows x 16 segs of 8 halves = 512 CP16
    #pragma unroll
    for (int i = 0; i < 2; ++i) {
        int e = tid + i * 256;
        int row = e >> 4, seg = e & 15;
        uint32_t off = (uint32_t)(row * 136 + seg * 8) * 2;
        CP16(base + 10240 + off, xhb + (size_t)(kc + row) * WID + j0 + seg * 8);
    }
}

__global__ __launch_bounds__(256, 2)
void qkv_gemm_mma(int bb)
{
    extern __shared__ char smem[];

    const int nt = blockIdx.x;
    const int my = blockIdx.y;
    const int b  = blockIdx.z + bb;
    const int g  = my >> 1;
    const int m0g = (my & 1) * 128;
    const int j0 = nt * 128;

    const __half* whg = g_wh + (size_t)g * CCH * CCH + (size_t)m0g * CCH;
    const __half* xhb = g_xh + (size_t)b * CCH * WID;

    const int tid  = threadIdx.x;
    const int lane = tid & 31;
    const int wid  = tid >> 5;
    const int wm   = wid >> 2;
    const int wn   = wid & 3;
    const int ltt  = lane >> 3;
    const int ltr  = lane & 7;

    float acc[4][4][4];
    #pragma unroll
    for (int i = 0; i < 4; ++i)
        #pragma unroll
        for (int j = 0; j < 4; ++j)
            #pragma unroll
            for (int r = 0; r < 4; ++r) acc[i][j][r] = 0.f;

    prefetch_chunk(smem, 0, tid, whg, xhb, 0, j0);
    CP_COMMIT();
    prefetch_chunk(smem, 1, tid, whg, xhb, 32, j0);
    CP_COMMIT();

    #pragma unroll 1
    for (int kc8 = 0; kc8 < 8; ++kc8) {
        const int stage = kc8 % 3;
        if (kc8 < 7) { CP_WAIT(1); } else { CP_WAIT(0); }
        __syncthreads();

        const char* sbuf = smem + stage * STAGE_BYTES;
        const __half* Ahp = (const __half*)(sbuf);
        const __half* Bhp = (const __half*)(sbuf + 10240);

        #pragma unroll
        for (int ks = 0; ks < 2; ++ks) {
            const int kb = ks * 16;
            uint32_t bh[4][2];
            #pragma unroll
            for (int np = 0; np < 2; ++np) {
                int krow = kb + (ltt & 1) * 8 + ltr;
                int ncol = wn * 32 + np * 16 + (ltt >> 1) * 8;
                ldsm_x4_t(sptr(Bhp + krow * 136 + ncol),
                          bh[np * 2][0], bh[np * 2][1],
                          bh[np * 2 + 1][0], bh[np * 2 + 1][1]);
            }
            uint32_t ah[4][4];
            #pragma unroll
            for (int ma = 0; ma < 4; ++ma) {
                int row = wm * 64 + ma * 16 + (ltt & 1) * 8 + ltr;
                int col = kb + (ltt >> 1) * 8;
                ldsm_x4(sptr(Ahp + row * 40 + col), ah[ma]);
            }
            #pragma unroll
            for (int ma = 0; ma < 4; ++ma)
                #pragma unroll
                for (int na = 0; na < 4; ++na)
                    mma_f16(acc[ma][na], ah[ma], bh[na][0], bh[na][1]);
        }
        __syncthreads();

        if (kc8 < 6) {
            prefetch_chunk(smem, (kc8 + 2) % 3, tid, whg, xhb, (kc8 + 2) * 32, j0);
            CP_COMMIT();
        }
    }

    #pragma unroll
    for (int ma = 0; ma < 4; ++ma) {
        int r0 = m0g + wm * 64 + ma * 16 + (lane >> 2);
        #pragma unroll
        for (int na = 0; na < 4; ++na) {
            int jj = j0 + wn * 32 + na * 8 + (lane & 3) * 2;
            float* d0 = g_qkv + ((size_t)(g * 256 + r0) * BATCH + b) * WID + jj;
            float* d1 = d0 + (size_t)8 * BATCH * WID;
            *(float2*)d0 = make_float2(acc[ma][na][0], acc[ma][na][1]);
            *(float2*)d1 = make_float2(acc[ma][na][2], acc[ma][na][3]);
        }
    }
}

// ---------------------------------------------------------------------------
// Kernel 2: windowed softmax, 8 outputs/thread, no max-sub, fast divide.
// ---------------------------------------------------------------------------
__global__ __launch_bounds__(256)
void attn_window8(float* __restrict__ out, int bb)
{
    int t8 = blockIdx.x * 256 + threadIdx.x;
    int w  = (t8 & 511) * 8;
    int t  = (t8 >> 9) + bb * 256;   // b*256 + o
    int o  = t & 255;
    int b  = t >> 8;

    const float* Q = g_qkv + ((size_t)o * BATCH + b) * WID;
    const float* K = Q + (size_t)256 * BATCH * WID;
    const float* V = Q + (size_t)512 * BATCH * WID;

    const float4 z4 = make_float4(0.f, 0.f, 0.f, 0.f);
    float4 q0 = *(const float4*)(Q + w);
    float4 q1 = *(const float4*)(Q + w + 4);
    float4 km = (w >= 4)      ? *(const float4*)(K + w - 4) : z4;
    float4 k0 = *(const float4*)(K + w);
    float4 k1 = *(const float4*)(K + w + 4);
    float4 kp = (w + 8 < WID) ? *(const float4*)(K + w + 8) : z4;
    float4 vm = (w >= 4)      ? *(const float4*)(V + w - 4) : z4;
    float4 v0 = *(const float4*)(V + w);
    float4 v1 = *(const float4*)(V + w + 4);
    float4 vp = (w + 8 < WID) ? *(const float4*)(V + w + 8) : z4;

    float kk[14] = {km.y, km.z, km.w, k0.x, k0.y, k0.z, k0.w,
                    k1.x, k1.y, k1.z, k1.w, kp.x, kp.y, kp.z};
    float vv[14] = {vm.y, vm.z, vm.w, v0.x, v0.y, v0.z, v0.w,
                    v1.x, v1.y, v1.z, v1.w, vp.x, vp.y, vp.z};
    float qv[8]  = {q0.x, q0.y, q0.z, q0.w, q1.x, q1.y, q1.z, q1.w};

    float res[8];
    #pragma unroll
    for (int tt = 0; tt < 8; ++tt) {
        float sum = 0.f, accn = 0.f;
        #pragma unroll
        for (int i = 0; i < 7; ++i) {
            float e = __expf(qv[tt] * kk[tt + i]);
            sum += e;
            accn = fmaf(e, vv[tt + i], accn);
        }
        res[tt] = __fdividef(accn, sum);
    }
    float* dst = out + (size_t)t * WID + w;
    *(float4*)dst       = make_float4(res[0], res[1], res[2], res[3]);
    *(float4*)(dst + 4) = make_float4(res[4], res[5], res[6], res[7]);
}

// ---------------------------------------------------------------------------
// Stream context (created at load time; no device memory). Chunks 1..3 run on
// priority-ordered side streams (chunk 0 on the capturing main stream).
// ---------------------------------------------------------------------------
namespace {
struct StreamCtx {
    cudaStream_t s[3];
    cudaEvent_t evFork, evConvW, evJoin[3];
    StreamCtx() {
        int lo = 0, hi = 0;
        cudaDeviceGetStreamPriorityRange(&lo, &hi);
        for (int i = 0; i < 3; ++i) {
            int pr = hi + 1 + i;
            if (pr > lo) pr = lo;
            cudaStreamCreateWithPriority(&s[i], cudaStreamNonBlocking, pr);
        }
        cudaEventCreateWithFlags(&evFork,  cudaEventDisableTiming);
        cudaEventCreateWithFlags(&evConvW, cudaEventDisableTiming);
        for (int i = 0; i < 3; ++i)
            cudaEventCreateWithFlags(&evJoin[i], cudaEventDisableTiming);
    }
};
StreamCtx g_sc;

cudaStream_t pick_main_stream() {
    cudaStreamCaptureStatus st = cudaStreamCaptureStatusNone;
    if (cudaStreamGetCaptureInfo(cudaStreamPerThread, &st) == cudaSuccess &&
        st == cudaStreamCaptureStatusActive)
        return cudaStreamPerThread;
    return cudaStreamLegacy;
}
} // namespace

// ---------------------------------------------------------------------------
extern "C" void kernel_launch(void* const* d_in, const int* in_sizes, int n_in,
                              void* d_out, int out_size)
{
    (void)in_sizes; (void)n_in; (void)out_size;
    const float* x  = (const float*)d_in[0];
    const float* wq = (const float*)d_in[1];
    const float* wk = (const float*)d_in[2];
    const float* wv = (const float*)d_in[3];
    float* out = (float*)d_out;

    cudaFuncSetAttribute(qkv_gemm_mma, cudaFuncAttributeMaxDynamicSharedMemorySize, SMEM_GEMM);

    cudaStream_t ms = pick_main_stream();

    // asymmetric chunks: head and tail small
    static const int bstart[4] = {0, 1, 4, 7};
    static const int bcount[4] = {1, 3, 3, 1};

    // fork
    cudaEventRecord(g_sc.evFork, ms);
    for (int i = 0; i < 3; ++i)
        cudaStreamWaitEvent(g_sc.s[i], g_sc.evFork, 0);

    // chunk 0 conversion (W + batch 0) on ms
    convert_h<<<(bcount[0] * NXB + 3 * NW4 + 255) / 256, 256, 0, ms>>>(
        x, wq, wk, wv, bcount[0] * NXB, 0, 1);
    cudaEventRecord(g_sc.evConvW, ms);

    // chunks 1..3 conversion on their streams (x only)
    for (int c = 1; c < 4; ++c)
        convert_h<<<(bcount[c] * NXB) / 256, 256, 0, g_sc.s[c - 1]>>>(
            x, wq, wk, wv, bcount[c] * NXB, bstart[c] * NXB, 0);

    // chunk 0 GEMM + attn on ms
    {
        dim3 grid(32, 6, bcount[0]);
        qkv_gemm_mma<<<grid, 256, SMEM_GEMM, ms>>>(bstart[0]);
        attn_window8<<<bcount[0] * 512, 256, 0, ms>>>(out, bstart[0]);
    }

    // chunks 1..3: wait W event, then GEMM + attn
    for (int c = 1; c < 4; ++c) {
        cudaStream_t st = g_sc.s[c - 1];
        cudaStreamWaitEvent(st, g_sc.evConvW, 0);
        dim3 grid(32, 6, bcount[c]);
        qkv_gemm_mma<<<grid, 256, SMEM_GEMM, st>>>(bstart[c]);
        attn_window8<<<bcount[c] * 512, 256, 0, st>>>(out, bstart[c]);
    }

    // join
    for (int c = 1; c < 4; ++c) {
        cudaEventRecord(g_sc.evJoin[c - 1], g_sc.s[c - 1]);
        cudaStreamWaitEvent(ms, g_sc.evJoin[c - 1], 0);
    }
}

// round 17
// speedup vs baseline: 2.3022x; 1.0210x over previous
#include <cuda_runtime.h>
#include <cuda_fp16.h>
#include <cstdint>

#define BATCH 8
#define CCH   256
#define WID   4096
#define GROUPS 3

// fp16 scratch: qkv[g*256+o][b][j]
__device__ __half g_qkv[(size_t)GROUPS * CCH * BATCH * WID];
// fp16-rounded operands (single digit)
__device__ __half g_xh[(size_t)BATCH * CCH * WID];
__device__ __half g_wh[(size_t)GROUPS * CCH * CCH];

// ---------------------------------------------------------------------------
__device__ __forceinline__ uint32_t sptr(const void* p) {
    return (uint32_t)__cvta_generic_to_shared(p);
}
__device__ __forceinline__ void ldsm_x4(uint32_t addr, uint32_t* r) {
    asm volatile("ldmatrix.sync.aligned.m8n8.x4.shared.b16 {%0,%1,%2,%3}, [%4];"
                 : "=r"(r[0]), "=r"(r[1]), "=r"(r[2]), "=r"(r[3]) : "r"(addr));
}
__device__ __forceinline__ void ldsm_x4_t(uint32_t addr, uint32_t& r0, uint32_t& r1,
                                          uint32_t& r2, uint32_t& r3) {
    asm volatile("ldmatrix.sync.aligned.m8n8.x4.trans.shared.b16 {%0,%1,%2,%3}, [%4];"
                 : "=r"(r0), "=r"(r1), "=r"(r2), "=r"(r3) : "r"(addr));
}
__device__ __forceinline__ void mma_f16(float* c, const uint32_t* a,
                                        uint32_t b0, uint32_t b1) {
    asm volatile(
        "mma.sync.aligned.m16n8k16.row.col.f32.f16.f16.f32 "
        "{%0,%1,%2,%3}, {%4,%5,%6,%7}, {%8,%9}, {%0,%1,%2,%3};"
        : "+f"(c[0]), "+f"(c[1]), "+f"(c[2]), "+f"(c[3])
        : "r"(a[0]), "r"(a[1]), "r"(a[2]), "r"(a[3]), "r"(b0), "r"(b1));
}
#define CP16(dst, src) \
    asm volatile("cp.async.cg.shared.global [%0], [%1], 16;" :: "r"(dst), "l"(src))
#define CP_COMMIT() asm volatile("cp.async.commit_group;")
#define CP_WAIT(n)  asm volatile("cp.async.wait_group %0;" :: "n"(n))

// ---------------------------------------------------------------------------
// Kernel 0: round x and W to fp16.
// ---------------------------------------------------------------------------
#define NX4 (BATCH * CCH * WID / 4)   // 2097152 float4 in x
#define NW4 (CCH * CCH / 4)           // 16384 float4 per weight
#define NXB (NX4 / 8)                 // 262144 float4 per batch

__global__ __launch_bounds__(256)
void convert_h(const float* __restrict__ x, const float* __restrict__ wq,
               const float* __restrict__ wk, const float* __restrict__ wv,
               int nx4, int xbase, int withW)
{
    int idx = blockIdx.x * 256 + threadIdx.x;
    if (idx < nx4) {
        int e = xbase + idx;
        float4 v = ((const float4*)x)[e];
        __half2 p01 = make_half2(__float2half_rn(v.x), __float2half_rn(v.y));
        __half2 p23 = make_half2(__float2half_rn(v.z), __float2half_rn(v.w));
        ((uint2*)g_xh)[e] = make_uint2(*(uint32_t*)&p01, *(uint32_t*)&p23);
    } else if (withW) {
        int r = idx - nx4;
        if (r < 3 * NW4) {
            int g = r / NW4, e = r % NW4;
            const float* W = (g == 0) ? wq : (g == 1) ? wk : wv;
            float4 v = ((const float4*)W)[e];
            __half2 p01 = make_half2(__float2half_rn(v.x), __float2half_rn(v.y));
            __half2 p23 = make_half2(__float2half_rn(v.z), __float2half_rn(v.w));
            ((uint2*)g_wh)[g * NW4 + e] =
                make_uint2(*(uint32_t*)&p01, *(uint32_t*)&p23);
        }
    }
}

// ---------------------------------------------------------------------------
// Kernel 1: fp16 GEMM, single pass. CTA 128m x 128n, k-chunk 32, 3-stage
// cp.async. Stage (18944 B): Ah[128][40]@0, Bh[32][136]@10240.
// Epilogue stores fp16 scratch (half the STG traffic).
// ---------------------------------------------------------------------------
#define STAGE_BYTES 18944
#define SMEM_GEMM   (3 * STAGE_BYTES)   // 56832

__device__ __forceinline__ void prefetch_chunk(
    char* s, int stage, int tid,
    const __half* __restrict__ whg, const __half* __restrict__ xhb,
    int kc, int j0)
{
    uint32_t base = sptr(s + stage * STAGE_BYTES);
    #pragma unroll
    for (int i = 0; i < 2; ++i) {
        int e = tid + i * 256;
        int row = e >> 2, seg = e & 3;
        uint32_t off = (uint32_t)(row * 40 + seg * 8) * 2;
        CP16(base + off, whg + (size_t)row * CCH + kc + seg * 8);
    }
    #pragma unroll
    for (int i = 0; i < 2; ++i) {
        int e = tid + i * 256;
        int row = e >> 4, seg = e & 15;
        uint32_t off = (uint32_t)(row * 136 + seg * 8) * 2;
        CP16(base + 10240 + off, xhb + (size_t)(kc + row) * WID + j0 + seg * 8);
    }
}

__global__ __launch_bounds__(256, 2)
void qkv_gemm_mma(int bb)
{
    extern __shared__ char smem[];

    const int nt = blockIdx.x;
    const int my = blockIdx.y;
    const int b  = blockIdx.z + bb;
    const int g  = my >> 1;
    const int m0g = (my & 1) * 128;
    const int j0 = nt * 128;

    const __half* whg = g_wh + (size_t)g * CCH * CCH + (size_t)m0g * CCH;
    const __half* xhb = g_xh + (size_t)b * CCH * WID;

    const int tid  = threadIdx.x;
    const int lane = tid & 31;
    const int wid  = tid >> 5;
    const int wm   = wid >> 2;
    const int wn   = wid & 3;
    const int ltt  = lane >> 3;
    const int ltr  = lane & 7;

    float acc[4][4][4];
    #pragma unroll
    for (int i = 0; i < 4; ++i)
        #pragma unroll
        for (int j = 0; j < 4; ++j)
            #pragma unroll
            for (int r = 0; r < 4; ++r) acc[i][j][r] = 0.f;

    prefetch_chunk(smem, 0, tid, whg, xhb, 0, j0);
    CP_COMMIT();
    prefetch_chunk(smem, 1, tid, whg, xhb, 32, j0);
    CP_COMMIT();

    #pragma unroll 1
    for (int kc8 = 0; kc8 < 8; ++kc8) {
        const int stage = kc8 % 3;
        if (kc8 < 7) { CP_WAIT(1); } else { CP_WAIT(0); }
        __syncthreads();

        const char* sbuf = smem + stage * STAGE_BYTES;
        const __half* Ahp = (const __half*)(sbuf);
        const __half* Bhp = (const __half*)(sbuf + 10240);

        #pragma unroll
        for (int ks = 0; ks < 2; ++ks) {
            const int kb = ks * 16;
            uint32_t bh[4][2];
            #pragma unroll
            for (int np = 0; np < 2; ++np) {
                int krow = kb + (ltt & 1) * 8 + ltr;
                int ncol = wn * 32 + np * 16 + (ltt >> 1) * 8;
                ldsm_x4_t(sptr(Bhp + krow * 136 + ncol),
                          bh[np * 2][0], bh[np * 2][1],
                          bh[np * 2 + 1][0], bh[np * 2 + 1][1]);
            }
            uint32_t ah[4][4];
            #pragma unroll
            for (int ma = 0; ma < 4; ++ma) {
                int row = wm * 64 + ma * 16 + (ltt & 1) * 8 + ltr;
                int col = kb + (ltt >> 1) * 8;
                ldsm_x4(sptr(Ahp + row * 40 + col), ah[ma]);
            }
            #pragma unroll
            for (int ma = 0; ma < 4; ++ma)
                #pragma unroll
                for (int na = 0; na < 4; ++na)
                    mma_f16(acc[ma][na], ah[ma], bh[na][0], bh[na][1]);
        }
        __syncthreads();

        if (kc8 < 6) {
            prefetch_chunk(smem, (kc8 + 2) % 3, tid, whg, xhb, (kc8 + 2) * 32, j0);
            CP_COMMIT();
        }
    }

    // epilogue: fp16 scratch stores
    #pragma unroll
    for (int ma = 0; ma < 4; ++ma) {
        int r0 = m0g + wm * 64 + ma * 16 + (lane >> 2);
        #pragma unroll
        for (int na = 0; na < 4; ++na) {
            int jj = j0 + wn * 32 + na * 8 + (lane & 3) * 2;
            __half* d0 = g_qkv + ((size_t)(g * 256 + r0) * BATCH + b) * WID + jj;
            __half* d1 = d0 + (size_t)8 * BATCH * WID;
            __half2 p0 = make_half2(__float2half_rn(acc[ma][na][0]),
                                    __float2half_rn(acc[ma][na][1]));
            __half2 p1 = make_half2(__float2half_rn(acc[ma][na][2]),
                                    __float2half_rn(acc[ma][na][3]));
            *(__half2*)d0 = p0;
            *(__half2*)d1 = p1;
        }
    }
}

// ---------------------------------------------------------------------------
// Kernel 2: windowed softmax, 8 outputs/thread, fp16 scratch loads.
// ---------------------------------------------------------------------------
__device__ __forceinline__ void h8_to_f(const uint4 v, float* f) {
    const __half2* p = (const __half2*)&v;
    #pragma unroll
    for (int i = 0; i < 4; ++i) {
        float2 t = __half22float2(p[i]);
        f[i * 2] = t.x; f[i * 2 + 1] = t.y;
    }
}

__global__ __launch_bounds__(256)
void attn_window8(float* __restrict__ out, int bb)
{
    int t8 = blockIdx.x * 256 + threadIdx.x;
    int w  = (t8 & 511) * 8;
    int t  = (t8 >> 9) + bb * 256;   // b*256 + o
    int o  = t & 255;
    int b  = t >> 8;

    const __half* Q = g_qkv + ((size_t)o * BATCH + b) * WID;
    const __half* K = Q + (size_t)256 * BATCH * WID;
    const __half* V = Q + (size_t)512 * BATCH * WID;

    const uint4 z = make_uint4(0, 0, 0, 0);
    uint4 qv8 = *(const uint4*)(Q + w);
    uint4 km8 = (w >= 8)        ? *(const uint4*)(K + w - 8) : z;
    uint4 k08 = *(const uint4*)(K + w);
    uint4 kp8 = (w + 8 < WID)   ? *(const uint4*)(K + w + 8) : z;
    uint4 vm8 = (w >= 8)        ? *(const uint4*)(V + w - 8) : z;
    uint4 v08 = *(const uint4*)(V + w);
    uint4 vp8 = (w + 8 < WID)   ? *(const uint4*)(V + w + 8) : z;

    float qv[8], km[8], k0[8], kp[8], vm[8], v0[8], vp[8];
    h8_to_f(qv8, qv);
    h8_to_f(km8, km); h8_to_f(k08, k0); h8_to_f(kp8, kp);
    h8_to_f(vm8, vm); h8_to_f(v08, v0); h8_to_f(vp8, vp);

    // kk/vv[i] corresponds to padded index w-3+i, i in [0,14)
    float kk[14] = {km[5], km[6], km[7], k0[0], k0[1], k0[2], k0[3],
                    k0[4], k0[5], k0[6], k0[7], kp[0], kp[1], kp[2]};
    float vv[14] = {vm[5], vm[6], vm[7], v0[0], v0[1], v0[2], v0[3],
                    v0[4], v0[5], v0[6], v0[7], vp[0], vp[1], vp[2]};

    float res[8];
    #pragma unroll
    for (int tt = 0; tt < 8; ++tt) {
        float sum = 0.f, accn = 0.f;
        #pragma unroll
        for (int i = 0; i < 7; ++i) {
            float e = __expf(qv[tt] * kk[tt + i]);
            sum += e;
            accn = fmaf(e, vv[tt + i], accn);
        }
        res[tt] = __fdividef(accn, sum);
    }
    float* dst = out + (size_t)t * WID + w;
    *(float4*)dst       = make_float4(res[0], res[1], res[2], res[3]);
    *(float4*)(dst + 4) = make_float4(res[4], res[5], res[6], res[7]);
}

// ---------------------------------------------------------------------------
// Stream context (created at load time; no device memory).
// ---------------------------------------------------------------------------
namespace {
struct StreamCtx {
    cudaStream_t s[3];
    cudaEvent_t evFork, evConvW, evJoin[3];
    StreamCtx() {
        int lo = 0, hi = 0;
        cudaDeviceGetStreamPriorityRange(&lo, &hi);
        for (int i = 0; i < 3; ++i) {
            int pr = hi + 1 + i;
            if (pr > lo) pr = lo;
            cudaStreamCreateWithPriority(&s[i], cudaStreamNonBlocking, pr);
        }
        cudaEventCreateWithFlags(&evFork,  cudaEventDisableTiming);
        cudaEventCreateWithFlags(&evConvW, cudaEventDisableTiming);
        for (int i = 0; i < 3; ++i)
            cudaEventCreateWithFlags(&evJoin[i], cudaEventDisableTiming);
    }
};
StreamCtx g_sc;

cudaStream_t pick_main_stream() {
    cudaStreamCaptureStatus st = cudaStreamCaptureStatusNone;
    if (cudaStreamGetCaptureInfo(cudaStreamPerThread, &st) == cudaSuccess &&
        st == cudaStreamCaptureStatusActive)
        return cudaStreamPerThread;
    return cudaStreamLegacy;
}
} // namespace

// ---------------------------------------------------------------------------
extern "C" void kernel_launch(void* const* d_in, const int* in_sizes, int n_in,
                              void* d_out, int out_size)
{
    (void)in_sizes; (void)n_in; (void)out_size;
    const float* x  = (const float*)d_in[0];
    const float* wq = (const float*)d_in[1];
    const float* wk = (const float*)d_in[2];
    const float* wv = (const float*)d_in[3];
    float* out = (float*)d_out;

    cudaFuncSetAttribute(qkv_gemm_mma, cudaFuncAttributeMaxDynamicSharedMemorySize, SMEM_GEMM);

    cudaStream_t ms = pick_main_stream();

    // asymmetric chunks: head and tail small
    static const int bstart[4] = {0, 1, 4, 7};
    static const int bcount[4] = {1, 3, 3, 1};

    // fork
    cudaEventRecord(g_sc.evFork, ms);
    for (int i = 0; i < 3; ++i)
        cudaStreamWaitEvent(g_sc.s[i], g_sc.evFork, 0);

    // chunk 0 conversion (W + batch 0) on ms
    convert_h<<<(bcount[0] * NXB + 3 * NW4 + 255) / 256, 256, 0, ms>>>(
        x, wq, wk, wv, bcount[0] * NXB, 0, 1);
    cudaEventRecord(g_sc.evConvW, ms);

    // chunks 1..3 conversion on their streams (x only)
    for (int c = 1; c < 4; ++c)
        convert_h<<<(bcount[c] * NXB) / 256, 256, 0, g_sc.s[c - 1]>>>(
            x, wq, wk, wv, bcount[c] * NXB, bstart[c] * NXB, 0);

    // chunk 0 GEMM + attn on ms
    {
        dim3 grid(32, 6, bcount[0]);
        qkv_gemm_mma<<<grid, 256, SMEM_GEMM, ms>>>(bstart[0]);
        attn_window8<<<bcount[0] * 512, 256, 0, ms>>>(out, bstart[0]);
    }

    // chunks 1..3: wait W event, then GEMM + attn
    for (int c = 1; c < 4; ++c) {
        cudaStream_t st = g_sc.s[c - 1];
        cudaStreamWaitEvent(st, g_sc.evConvW, 0);
        dim3 grid(32, 6, bcount[c]);
        qkv_gemm_mma<<<grid, 256, SMEM_GEMM, st>>>(bstart[c]);
        attn_window8<<<bcount[c] * 512, 256, 0, st>>>(out, bstart[c]);
    }

    // join
    for (int c = 1; c < 4; ++c) {
        cudaEventRecord(g_sc.evJoin[c - 1], g_sc.s[c - 1]);
        cudaStreamWaitEvent(ms, g_sc.evJoin[c - 1], 0);
    }
}